// round 2
// baseline (speedup 1.0000x reference)
#include <cuda_runtime.h>
#include <math.h>

// ---------------- scratch (no allocations allowed) ----------------
#define TABLE_N 8192
#define MAX_TAB 4.5f
#define HID 100
#define MAXN 65536
#define MAXG 256

__device__ __align__(16) float g_table[2 * (TABLE_N + 2)];   // interleaved (w0, w1)
__device__ __align__(16) float g_agg[MAXN * 4];              // scatter-add target [N,4]
__device__ float g_sums[MAXG * 16];            // pooled sums [G,16]
__device__ float g_cnt[MAXG];                  // node counts per graph
__device__ int   g_b64;                        // 1 if batch array is int64

__device__ __forceinline__ float swishf(float x) {
    return x / (1.0f + __expf(-x));
}

// ---------------- zero scratch ----------------
__global__ void zero_kernel(int nagg, int nsum, int ncnt) {
    int i = blockIdx.x * blockDim.x + threadIdx.x;
    if (i < nagg) g_agg[i] = 0.0f;
    if (i < nsum) g_sums[i] = 0.0f;
    if (i < ncnt) g_cnt[i] = 0.0f;
}

// ---------------- detect batch dtype (int32 vs int64) ----------------
// batch is sorted graph ids in [0, G). If stored as little-endian int64, every
// odd 32-bit word is a zero high-word. If int32, odd words deep in the array
// hold graph ids >= 1 (each graph holds ~N/G << N/4 nodes). Probe 3 odd words.
__global__ void detect_kernel(const int* __restrict__ bw, int n) {
    if (threadIdx.x == 0 && blockIdx.x == 0) {
        int i1 = (n / 4) | 1;
        int i2 = (n / 2) | 1;
        int i3 = (3 * n / 4) | 1;
        g_b64 = (bw[i1] == 0 && bw[i2] == 0 && bw[i3] == 0) ? 1 : 0;
    }
}

// ---------------- build radial-MLP lookup table ----------------
// w(d) = swish(swish(basis(d) @ rw1 + rb1) @ rw2 + rb2) @ rw3, tabulated on
// d in [0, 4.5] (basis identically 0 beyond 4.5 -> w constant; clamp handles it).
__global__ void build_table(const float* __restrict__ rw1, const float* __restrict__ rb1,
                            const float* __restrict__ rw2, const float* __restrict__ rb2,
                            const float* __restrict__ rw3) {
    int idx = blockIdx.x * blockDim.x + threadIdx.x;
    if (idx > TABLE_N) return;
    float d = (MAX_TAB / (float)TABLE_N) * (float)idx;

    float basis[3];
#pragma unroll
    for (int b = 0; b < 3; b++) {
        float diff = (d - 1.5f * (float)b) * (1.0f / 1.5f);
        float c = cospif(0.5f * diff);
        basis[b] = (fabsf(diff) < 1.0f) ? c * c : 0.0f;
    }

    float h1[HID];
#pragma unroll 4
    for (int j = 0; j < HID; j++) {
        float acc = rb1[j];
#pragma unroll
        for (int b = 0; b < 3; b++) acc = fmaf(basis[b], rw1[b * HID + j], acc);
        h1[j] = swishf(acc);
    }

    float w0 = 0.0f, w1 = 0.0f;
    for (int j = 0; j < HID; j++) {
        float acc = rb2[j];
#pragma unroll 4
        for (int i = 0; i < HID; i++) acc = fmaf(h1[i], rw2[i * HID + j], acc);
        float s = swishf(acc);
        w0 = fmaf(s, rw3[2 * j], w0);
        w1 = fmaf(s, rw3[2 * j + 1], w1);
    }
    g_table[2 * idx]     = w0;
    g_table[2 * idx + 1] = w1;
}

// ---------------- per-edge: distance -> table lerp -> message scatter ----------------
__global__ void edge_kernel(const float* __restrict__ pos, const float* __restrict__ z,
                            const float* __restrict__ eattr, const int* __restrict__ eidx,
                            int E) {
    int e = blockIdx.x * blockDim.x + threadIdx.x;
    if (e >= E) return;
    int s = eidx[e];
    int t = eidx[E + e];

    float sx = __ldg(&pos[3 * s]);
    float sy = __ldg(&pos[3 * s + 1]);
    float sz = __ldg(&pos[3 * s + 2]);
    float dx = sx - __ldg(&pos[3 * t]);
    float dy = sy - __ldg(&pos[3 * t + 1]);
    float dz = sz - __ldg(&pos[3 * t + 2]);
    float d = sqrtf(fmaf(dx, dx, fmaf(dy, dy, fmaf(dz, dz, 1e-12f))));

    float u = d * ((float)TABLE_N / MAX_TAB);
    u = fminf(u, (float)TABLE_N);
    int i0 = min((int)u, TABLE_N - 1);
    float f = u - (float)i0;
    float2 ta = *(const float2*)&g_table[2 * i0];
    float2 tb = *(const float2*)&g_table[2 * i0 + 2];
    float w0 = fmaf(f, tb.x - ta.x, ta.x);
    float w1 = fmaf(f, tb.y - ta.y, ta.y);

    float a  = eattr[e];
    float zs = __ldg(&z[s]);
    float cv = w0 * a;

    // single vectorized reduction: 1/4 the atomic ops vs 4x scalar atomicAdd
    float m0 = cv * sx, m1 = cv * sy, m2 = cv * sz, m3 = w1 * a * zs;
    asm volatile("red.global.add.v4.f32 [%0], {%1, %2, %3, %4};"
                 :: "l"(&g_agg[4 * t]), "f"(m0), "f"(m1), "f"(m2), "f"(m3)
                 : "memory");
}

// ---------------- per-node MLP + warp-aggregated graph pooling ----------------
__global__ void node_kernel(const float* __restrict__ lw1, const float* __restrict__ lb1,
                            const float* __restrict__ lw2, const float* __restrict__ lb2,
                            const int* __restrict__ bw, int n, float inv_norm) {
    __shared__ float s_w1[4 * 32];
    __shared__ float s_b1[32];
    __shared__ float s_w2[32 * 16];
    __shared__ float s_b2[16];
    int tid = threadIdx.x;
    for (int i = tid; i < 128; i += blockDim.x) s_w1[i] = lw1[i];
    for (int i = tid; i < 512; i += blockDim.x) s_w2[i] = lw2[i];
    if (tid < 32) s_b1[tid] = lb1[tid];
    if (tid < 16) s_b2[tid] = lb2[tid];
    __syncthreads();

    int i = blockIdx.x * blockDim.x + tid;
    bool valid = (i < n);
    int g = 0;
    float h2[16];
#pragma unroll
    for (int j = 0; j < 16; j++) h2[j] = 0.0f;

    if (valid) {
        float4 av = *(const float4*)&g_agg[4 * i];
        float a0 = fmaxf(av.x * inv_norm, 0.0f);
        float a1 = fmaxf(av.y * inv_norm, 0.0f);
        float a2 = fmaxf(av.z * inv_norm, 0.0f);
        float a3 = fmaxf(av.w * inv_norm, 0.0f);
        float h1[32];
#pragma unroll
        for (int j = 0; j < 32; j++) {
            float acc = s_b1[j];
            acc = fmaf(a0, s_w1[j], acc);
            acc = fmaf(a1, s_w1[32 + j], acc);
            acc = fmaf(a2, s_w1[64 + j], acc);
            acc = fmaf(a3, s_w1[96 + j], acc);
            h1[j] = fmaxf(acc, 0.0f);
        }
#pragma unroll
        for (int j = 0; j < 16; j++) {
            float acc = s_b2[j];
#pragma unroll
            for (int c = 0; c < 32; c++) acc = fmaf(h1[c], s_w2[c * 16 + j], acc);
            h2[j] = fmaxf(acc, 0.0f);
        }
        g = g_b64 ? bw[2 * i] : bw[i];
    }

    // batch is sorted -> whole warps usually share g: warp-reduce, 32x fewer atomics
    unsigned full = 0xffffffffu;
    unsigned mask = __ballot_sync(full, valid);
    int lane = tid & 31;
    int g0 = __shfl_sync(full, g, 0);
    bool allsame = (mask == full) && __all_sync(full, g == g0);
    if (allsame) {
#pragma unroll
        for (int j = 0; j < 16; j++) {
            float v = h2[j];
#pragma unroll
            for (int o = 16; o > 0; o >>= 1) v += __shfl_xor_sync(full, v, o);
            if (lane == j) atomicAdd(&g_sums[g0 * 16 + j], v);
        }
        if (lane == 0) atomicAdd(&g_cnt[g0], 32.0f);
    } else if (valid) {
#pragma unroll
        for (int j = 0; j < 16; j++) atomicAdd(&g_sums[g * 16 + j], h2[j]);
        atomicAdd(&g_cnt[g], 1.0f);
    }
}

// ---------------- per-graph head ----------------
__global__ void final_kernel(const float* __restrict__ fw1, const float* __restrict__ fb1,
                             const float* __restrict__ fw2, const float* __restrict__ fb2,
                             float* __restrict__ out, int G) {
    int g = blockIdx.x * blockDim.x + threadIdx.x;
    if (g >= G) return;
    float c = fmaxf(g_cnt[g], 1.0f);
    float inv = 1.0f / c;
    float p[16];
#pragma unroll
    for (int j = 0; j < 16; j++) p[j] = g_sums[g * 16 + j] * inv;
    float t[32];
#pragma unroll
    for (int j = 0; j < 32; j++) {
        float acc = fb1[j];
#pragma unroll
        for (int c2 = 0; c2 < 16; c2++) acc = fmaf(p[c2], fw1[c2 * 32 + j], acc);
        t[j] = fmaxf(acc, 0.0f);
    }
#pragma unroll
    for (int k = 0; k < 3; k++) {
        float acc = fb2[k];
#pragma unroll
        for (int c2 = 0; c2 < 32; c2++) acc = fmaf(t[c2], fw2[c2 * 3 + k], acc);
        out[g * 3 + k] = acc;
    }
}

// ---------------- launch ----------------
extern "C" void kernel_launch(void* const* d_in, const int* in_sizes, int n_in,
                              void* d_out, int out_size) {
    const float* pos   = (const float*)d_in[0];
    const float* z     = (const float*)d_in[1];
    const float* eattr = (const float*)d_in[2];
    const int*   eidx  = (const int*)d_in[3];
    const int*   bw    = (const int*)d_in[4];   // batch words (int32 or int64; probed)
    const float* rw1 = (const float*)d_in[5];
    const float* rb1 = (const float*)d_in[6];
    const float* rw2 = (const float*)d_in[7];
    const float* rb2 = (const float*)d_in[8];
    const float* rw3 = (const float*)d_in[9];
    const float* lw1 = (const float*)d_in[10];
    const float* lb1 = (const float*)d_in[11];
    const float* lw2 = (const float*)d_in[12];
    const float* lb2 = (const float*)d_in[13];
    const float* fw1 = (const float*)d_in[14];
    const float* fb1 = (const float*)d_in[15];
    const float* fw2 = (const float*)d_in[16];
    const float* fb2 = (const float*)d_in[17];

    int n = in_sizes[1];          // N nodes (z has N elements)
    int E = in_sizes[2];          // edges (edge_attr has E elements)
    int G = out_size / 3;         // graphs
    float inv_norm = sqrtf((float)n / (float)E);   // agg / sqrt(E/N)

    int nagg = n * 4;
    zero_kernel<<<(nagg + 255) / 256, 256>>>(nagg, G * 16, G);
    detect_kernel<<<1, 32>>>(bw, n);
    build_table<<<(TABLE_N + 1 + 127) / 128, 128>>>(rw1, rb1, rw2, rb2, rw3);
    edge_kernel<<<(E + 255) / 256, 256>>>(pos, z, eattr, eidx, E);
    node_kernel<<<(n + 255) / 256, 256>>>(lw1, lb1, lw2, lb2, bw, n, inv_norm);
    final_kernel<<<(G + 63) / 64, 64>>>(fw1, fb1, fw2, fb2, (float*)d_out, G);
}

// round 3
// speedup vs baseline: 3.3626x; 3.3626x over previous
#include <cuda_runtime.h>
#include <math.h>

// ---------------- scratch (no allocations allowed) ----------------
#define TABLE_N 2048
#define MAX_TAB 4.5f
#define HID 100
#define TILE 32
#define MAXN 65536
#define MAXG 256

__device__ __align__(16) float2 g_tabc[TABLE_N + 2];   // compact (w0,w1) per grid point
__device__ __align__(16) float4 g_tab4[TABLE_N + 1];   // (w0_i,w1_i,w0_{i+1},w1_{i+1})
__device__ __align__(16) float4 g_node4[MAXN];         // packed (pos.xyz, z)
__device__ __align__(16) float g_agg[MAXN * 4];        // scatter-add target [N,4]
__device__ float g_sums[MAXG * 16];                    // pooled sums [G,16]
__device__ float g_cnt[MAXG];                          // node counts per graph
__device__ int   g_b64;                                // 1 if batch array is int64

__device__ __forceinline__ float swishf(float x) {
    return x / (1.0f + __expf(-x));
}

// ---------------- prep: pack nodes, zero scratch, probe batch dtype ----------------
__global__ void prep_kernel(const float* __restrict__ pos, const float* __restrict__ z,
                            const int* __restrict__ bw, int n, int G) {
    int i = blockIdx.x * blockDim.x + threadIdx.x;
    if (i < n) {
        g_node4[i] = make_float4(pos[3 * i], pos[3 * i + 1], pos[3 * i + 2], z[i]);
        ((float4*)g_agg)[i] = make_float4(0.f, 0.f, 0.f, 0.f);
    }
    if (i < G * 16) g_sums[i] = 0.0f;
    if (i < G) g_cnt[i] = 0.0f;
    if (i == 0) {
        // batch sorted in [0,G). int64 little-endian -> odd words are zero high-words.
        int i1 = (n / 4) | 1, i2 = (n / 2) | 1, i3 = (3 * n / 4) | 1;
        g_b64 = (bw[i1] == 0 && bw[i2] == 0 && bw[i3] == 0) ? 1 : 0;
    }
}

// ---------------- cooperative radial-MLP table build ----------------
// Block of 128 threads computes TILE=32 consecutive table entries.
// Stage 1: h1[e][j] = swish(basis(d_e) @ rw1 + rb1) into smem.
// Stage 2: thread j accumulates layer-2 unit j for all 32 entries (coalesced rw2
// rows, broadcast smem h1), then warp-shuffle + smem partial reduction into (w0,w1).
__global__ void build_table(const float* __restrict__ rw1, const float* __restrict__ rb1,
                            const float* __restrict__ rw2, const float* __restrict__ rb2,
                            const float* __restrict__ rw3) {
    __shared__ float s_h1[TILE * HID];
    __shared__ float s_part[4][TILE][2];
    int tid = threadIdx.x;
    int base = blockIdx.x * TILE;

    // stage 1: 3200 (e,j) pairs over 128 threads
    for (int p = tid; p < TILE * HID; p += 128) {
        int e = p / HID, j = p - e * HID;
        float d = (MAX_TAB / (float)TABLE_N) * (float)(base + e);
        float acc = rb1[j];
#pragma unroll
        for (int b = 0; b < 3; b++) {
            float diff = (d - 1.5f * (float)b) * (1.0f / 1.5f);
            float c = cospif(0.5f * diff);
            float bas = (fabsf(diff) < 1.0f) ? c * c : 0.0f;
            acc = fmaf(bas, rw1[b * HID + j], acc);
        }
        s_h1[p] = swishf(acc);
    }
    __syncthreads();

    // stage 2: all 128 threads participate; j >= HID contributes zero
    bool live = (tid < HID);
    int jj = live ? tid : 0;
    float acc[TILE];
    float b2 = live ? rb2[jj] : 0.0f;
#pragma unroll
    for (int e = 0; e < TILE; e++) acc[e] = b2;
    for (int i = 0; i < HID; i++) {
        float w = rw2[i * HID + jj];          // coalesced row read, broadcast-safe
#pragma unroll
        for (int e = 0; e < TILE; e++) acc[e] = fmaf(s_h1[e * HID + i], w, acc[e]);
    }
    float r0 = live ? rw3[2 * jj] : 0.0f;
    float r1 = live ? rw3[2 * jj + 1] : 0.0f;
    int lane = tid & 31, wid = tid >> 5;
#pragma unroll
    for (int e = 0; e < TILE; e++) {
        float s = swishf(acc[e]);
        float v0 = s * r0, v1 = s * r1;
#pragma unroll
        for (int o = 16; o > 0; o >>= 1) {
            v0 += __shfl_xor_sync(0xffffffffu, v0, o);
            v1 += __shfl_xor_sync(0xffffffffu, v1, o);
        }
        if (lane == 0) { s_part[wid][e][0] = v0; s_part[wid][e][1] = v1; }
    }
    __syncthreads();
    if (tid < TILE) {
        int idx = base + tid;
        if (idx <= TABLE_N) {
            float w0 = s_part[0][tid][0] + s_part[1][tid][0] + s_part[2][tid][0] + s_part[3][tid][0];
            float w1 = s_part[0][tid][1] + s_part[1][tid][1] + s_part[2][tid][1] + s_part[3][tid][1];
            g_tabc[idx] = make_float2(w0, w1);
        }
    }
}

// ---------------- duplicate table into float4 for single-load lerp ----------------
__global__ void tab_pack(int dummy) {
    int i = blockIdx.x * blockDim.x + threadIdx.x;
    if (i < TABLE_N) {
        float2 a = g_tabc[i], b = g_tabc[i + 1];
        g_tab4[i] = make_float4(a.x, a.y, b.x, b.y);
    }
}

// ---------------- per-edge: distance -> table lerp -> message scatter ----------------
__global__ void edge_kernel(const float* __restrict__ eattr, const int* __restrict__ eidx,
                            int E) {
    int e = blockIdx.x * blockDim.x + threadIdx.x;
    if (e >= E) return;
    int s = eidx[e];
    int t = eidx[E + e];

    float4 ns = __ldg(&g_node4[s]);
    float4 nt = __ldg(&g_node4[t]);
    float dx = ns.x - nt.x;
    float dy = ns.y - nt.y;
    float dz = ns.z - nt.z;
    float d = sqrtf(fmaf(dx, dx, fmaf(dy, dy, fmaf(dz, dz, 1e-12f))));

    float u = d * ((float)TABLE_N / MAX_TAB);
    u = fminf(u, (float)TABLE_N);
    int i0 = min((int)u, TABLE_N - 1);
    float f = u - (float)i0;
    float4 tv = __ldg(&g_tab4[i0]);
    float w0 = fmaf(f, tv.z - tv.x, tv.x);
    float w1 = fmaf(f, tv.w - tv.y, tv.y);

    float a  = eattr[e];
    float cv = w0 * a;
    float m0 = cv * ns.x, m1 = cv * ns.y, m2 = cv * ns.z, m3 = w1 * a * ns.w;
    asm volatile("red.global.add.v4.f32 [%0], {%1, %2, %3, %4};"
                 :: "l"(&g_agg[4 * t]), "f"(m0), "f"(m1), "f"(m2), "f"(m3)
                 : "memory");
}

// ---------------- per-node MLP + warp-aggregated graph pooling ----------------
__global__ void node_kernel(const float* __restrict__ lw1, const float* __restrict__ lb1,
                            const float* __restrict__ lw2, const float* __restrict__ lb2,
                            const int* __restrict__ bw, int n, float inv_norm) {
    __shared__ float s_w1[4 * 32];
    __shared__ float s_b1[32];
    __shared__ float s_w2[32 * 16];
    __shared__ float s_b2[16];
    int tid = threadIdx.x;
    for (int i = tid; i < 128; i += blockDim.x) s_w1[i] = lw1[i];
    for (int i = tid; i < 512; i += blockDim.x) s_w2[i] = lw2[i];
    if (tid < 32) s_b1[tid] = lb1[tid];
    if (tid < 16) s_b2[tid] = lb2[tid];
    __syncthreads();

    int i = blockIdx.x * blockDim.x + tid;
    bool valid = (i < n);
    int g = 0;
    float h2[16];
#pragma unroll
    for (int j = 0; j < 16; j++) h2[j] = 0.0f;

    if (valid) {
        float4 av = *(const float4*)&g_agg[4 * i];
        float a0 = fmaxf(av.x * inv_norm, 0.0f);
        float a1 = fmaxf(av.y * inv_norm, 0.0f);
        float a2 = fmaxf(av.z * inv_norm, 0.0f);
        float a3 = fmaxf(av.w * inv_norm, 0.0f);
        float h1[32];
#pragma unroll
        for (int j = 0; j < 32; j++) {
            float acc = s_b1[j];
            acc = fmaf(a0, s_w1[j], acc);
            acc = fmaf(a1, s_w1[32 + j], acc);
            acc = fmaf(a2, s_w1[64 + j], acc);
            acc = fmaf(a3, s_w1[96 + j], acc);
            h1[j] = fmaxf(acc, 0.0f);
        }
#pragma unroll
        for (int j = 0; j < 16; j++) {
            float acc = s_b2[j];
#pragma unroll
            for (int c = 0; c < 32; c++) acc = fmaf(h1[c], s_w2[c * 16 + j], acc);
            h2[j] = fmaxf(acc, 0.0f);
        }
        g = g_b64 ? bw[2 * i] : bw[i];
    }

    // batch sorted -> whole warps usually share g: warp-reduce, 32x fewer atomics
    unsigned full = 0xffffffffu;
    unsigned mask = __ballot_sync(full, valid);
    int lane = tid & 31;
    int g0 = __shfl_sync(full, g, 0);
    bool allsame = (mask == full) && __all_sync(full, g == g0);
    if (allsame) {
#pragma unroll
        for (int j = 0; j < 16; j++) {
            float v = h2[j];
#pragma unroll
            for (int o = 16; o > 0; o >>= 1) v += __shfl_xor_sync(full, v, o);
            if (lane == j) atomicAdd(&g_sums[g0 * 16 + j], v);
        }
        if (lane == 0) atomicAdd(&g_cnt[g0], 32.0f);
    } else if (valid) {
#pragma unroll
        for (int j = 0; j < 16; j++) atomicAdd(&g_sums[g * 16 + j], h2[j]);
        atomicAdd(&g_cnt[g], 1.0f);
    }
}

// ---------------- per-graph head ----------------
__global__ void final_kernel(const float* __restrict__ fw1, const float* __restrict__ fb1,
                             const float* __restrict__ fw2, const float* __restrict__ fb2,
                             float* __restrict__ out, int G) {
    int g = blockIdx.x * blockDim.x + threadIdx.x;
    if (g >= G) return;
    float c = fmaxf(g_cnt[g], 1.0f);
    float inv = 1.0f / c;
    float p[16];
#pragma unroll
    for (int j = 0; j < 16; j++) p[j] = g_sums[g * 16 + j] * inv;
    float t[32];
#pragma unroll
    for (int j = 0; j < 32; j++) {
        float acc = fb1[j];
#pragma unroll
        for (int c2 = 0; c2 < 16; c2++) acc = fmaf(p[c2], fw1[c2 * 32 + j], acc);
        t[j] = fmaxf(acc, 0.0f);
    }
#pragma unroll
    for (int k = 0; k < 3; k++) {
        float acc = fb2[k];
#pragma unroll
        for (int c2 = 0; c2 < 32; c2++) acc = fmaf(t[c2], fw2[c2 * 3 + k], acc);
        out[g * 3 + k] = acc;
    }
}

// ---------------- launch ----------------
extern "C" void kernel_launch(void* const* d_in, const int* in_sizes, int n_in,
                              void* d_out, int out_size) {
    const float* pos   = (const float*)d_in[0];
    const float* z     = (const float*)d_in[1];
    const float* eattr = (const float*)d_in[2];
    const int*   eidx  = (const int*)d_in[3];
    const int*   bw    = (const int*)d_in[4];   // batch words (int32 or int64; probed)
    const float* rw1 = (const float*)d_in[5];
    const float* rb1 = (const float*)d_in[6];
    const float* rw2 = (const float*)d_in[7];
    const float* rb2 = (const float*)d_in[8];
    const float* rw3 = (const float*)d_in[9];
    const float* lw1 = (const float*)d_in[10];
    const float* lb1 = (const float*)d_in[11];
    const float* lw2 = (const float*)d_in[12];
    const float* lb2 = (const float*)d_in[13];
    const float* fw1 = (const float*)d_in[14];
    const float* fb1 = (const float*)d_in[15];
    const float* fw2 = (const float*)d_in[16];
    const float* fb2 = (const float*)d_in[17];

    int n = in_sizes[1];          // N nodes (z has N elements)
    int E = in_sizes[2];          // edges (edge_attr has E elements)
    int G = out_size / 3;         // graphs
    float inv_norm = sqrtf((float)n / (float)E);   // agg / sqrt(E/N)

    prep_kernel<<<(n + 255) / 256, 256>>>(pos, z, bw, n, G);
    build_table<<<(TABLE_N + 1 + TILE - 1) / TILE, 128>>>(rw1, rb1, rw2, rb2, rw3);
    tab_pack<<<(TABLE_N + 255) / 256, 256>>>(0);
    edge_kernel<<<(E + 255) / 256, 256>>>(eattr, eidx, E);
    node_kernel<<<(n + 255) / 256, 256>>>(lw1, lb1, lw2, lb2, bw, n, inv_norm);
    final_kernel<<<(G + 63) / 64, 64>>>(fw1, fb1, fw2, fb2, (float*)d_out, G);
}

// round 6
// speedup vs baseline: 5.0320x; 1.4964x over previous
#include <cuda_runtime.h>
#include <math.h>

// ---------------- scratch (no allocations allowed) ----------------
#define TABLE_N 1024
#define MAX_TAB 4.5f
#define HID 100
#define TILE 16            // table entries per build block (computes TILE+1)
#define MAXN 65536
#define MAXG 256

__device__ __align__(16) float4 g_tab4[TABLE_N + 1];   // (w0_i,w1_i,w0_{i+1},w1_{i+1})
__device__ __align__(16) float4 g_node4[MAXN];         // packed (pos.xyz, z)
__device__ __align__(16) float g_agg[MAXN * 4];        // scatter-add target [N,4]
__device__ float g_sums[MAXG * 16];                    // pooled sums [G,16]
__device__ float g_cnt[MAXG];                          // node counts per graph
__device__ int   g_b64;                                // 1 if batch array is int64
__device__ int   g_done;                               // node-block completion counter

__device__ __forceinline__ float swishf(float x) {
    return x / (1.0f + __expf(-x));
}

// ================= kernel 1: prep (pack/zero/probe) + build table ==============
// Blocks [0, bprep): pack nodes + zero scratch.  Blocks [bprep, bprep+NB): table.
__global__ void prep_build_kernel(const float* __restrict__ pos, const float* __restrict__ z,
                                  const int* __restrict__ bw, int n, int G, int bprep,
                                  const float* __restrict__ rw1, const float* __restrict__ rb1,
                                  const float* __restrict__ rw2, const float* __restrict__ rb2,
                                  const float* __restrict__ rw3) {
    __shared__ float s_h1[(TILE + 1) * HID];        // stage1 out; reused for half-sums
    __shared__ float s_part[4][TILE + 1][2];
    __shared__ float s_w[TILE + 1][2];
    int tid = threadIdx.x;

    if (blockIdx.x < (unsigned)bprep) {
        int i = blockIdx.x * 256 + tid;
        if (i < n) {
            g_node4[i] = make_float4(pos[3 * i], pos[3 * i + 1], pos[3 * i + 2], z[i]);
            ((float4*)g_agg)[i] = make_float4(0.f, 0.f, 0.f, 0.f);
        }
        if (i < G * 16) g_sums[i] = 0.0f;
        if (i < G) g_cnt[i] = 0.0f;
        if (i == 0) {
            g_done = 0;
            // batch sorted in [0,G). int64 LE -> odd words are zero high-words.
            int i1 = (n / 4) | 1, i2 = (n / 2) | 1, i3 = (3 * n / 4) | 1;
            g_b64 = (bw[i1] == 0 && bw[i2] == 0 && bw[i3] == 0) ? 1 : 0;
        }
        return;
    }

    // ---------- table build: TILE+1 entries per block ----------
    int base = (blockIdx.x - bprep) * TILE;
    const int EC = TILE + 1;

    // stage 1: h1[e][i] = swish(basis(d_e) @ rw1 + rb1),  EC*HID pairs / 256 thr
    for (int p = tid; p < EC * HID; p += 256) {
        int e = p / HID, j = p - e * HID;
        float d = (MAX_TAB / (float)TABLE_N) * (float)(base + e);
        float acc = rb1[j];
#pragma unroll
        for (int b = 0; b < 3; b++) {
            float diff = (d - 1.5f * (float)b) * (1.0f / 1.5f);
            float c = cospif(0.5f * diff);
            float bas = (fabsf(diff) < 1.0f) ? c * c : 0.0f;
            acc = fmaf(bas, rw1[b * HID + j], acc);
        }
        s_h1[p] = swishf(acc);
    }
    __syncthreads();

    // stage 2: split the i-sum across two halves (tid>>7), j = tid & 127
    int jj = tid & 127;
    int half = tid >> 7;                  // 0 or 1
    bool live = (jj < HID);
    int j = live ? jj : 0;
    float acc[EC];
    float init = (live && half == 0) ? rb2[j] : 0.0f;
#pragma unroll
    for (int e = 0; e < EC; e++) acc[e] = init;
    int i0 = half * (HID / 2), i1 = i0 + (HID / 2);
    if (live) {
        for (int i = i0; i < i1; i++) {
            float w = rw2[i * HID + j];
#pragma unroll
            for (int e = 0; e < EC; e++) acc[e] = fmaf(s_h1[e * HID + i], w, acc[e]);
        }
    }
    __syncthreads();          // s_h1 free; reuse for half-1 partials
    if (half == 1 && live) {
#pragma unroll
        for (int e = 0; e < EC; e++) s_h1[j * EC + e] = acc[e];
    }
    __syncthreads();

    if (half == 0) {
        float r0 = live ? rw3[2 * j] : 0.0f;
        float r1 = live ? rw3[2 * j + 1] : 0.0f;
        int lane = tid & 31, wid = tid >> 5;   // warps 0..3
#pragma unroll
        for (int e = 0; e < EC; e++) {
            float tot = acc[e] + (live ? s_h1[j * EC + e] : 0.0f);
            float s = live ? swishf(tot) : 0.0f;
            float v0 = s * r0, v1 = s * r1;
#pragma unroll
            for (int o = 16; o > 0; o >>= 1) {
                v0 += __shfl_xor_sync(0xffffffffu, v0, o);
                v1 += __shfl_xor_sync(0xffffffffu, v1, o);
            }
            if (lane == 0) { s_part[wid][e][0] = v0; s_part[wid][e][1] = v1; }
        }
    }
    __syncthreads();
    if (tid < EC) {
        s_w[tid][0] = s_part[0][tid][0] + s_part[1][tid][0] + s_part[2][tid][0] + s_part[3][tid][0];
        s_w[tid][1] = s_part[0][tid][1] + s_part[1][tid][1] + s_part[2][tid][1] + s_part[3][tid][1];
    }
    __syncthreads();
    if (tid < TILE) {
        int idx = base + tid;
        if (idx < TABLE_N)
            g_tab4[idx] = make_float4(s_w[tid][0], s_w[tid][1], s_w[tid + 1][0], s_w[tid + 1][1]);
    }
}

// ================= kernel 2: per-edge, persistent, smem table ==============
__global__ void edge_kernel(const float* __restrict__ eattr, const int* __restrict__ eidx,
                            int E) {
    __shared__ float4 s_tab[TABLE_N];
    int tid = threadIdx.x;
    for (int i = tid; i < TABLE_N; i += blockDim.x) s_tab[i] = __ldg(&g_tab4[i]);
    __syncthreads();

    int stride = gridDim.x * blockDim.x;
    for (int e = blockIdx.x * blockDim.x + tid; e < E; e += stride) {
        int s = eidx[e];
        int t = eidx[E + e];

        float4 ns = __ldg(&g_node4[s]);
        float4 nt = __ldg(&g_node4[t]);
        float dx = ns.x - nt.x;
        float dy = ns.y - nt.y;
        float dz = ns.z - nt.z;
        float d = sqrtf(fmaf(dx, dx, fmaf(dy, dy, fmaf(dz, dz, 1e-12f))));

        float u = d * ((float)TABLE_N / MAX_TAB);
        u = fminf(u, (float)TABLE_N);
        int i0 = min((int)u, TABLE_N - 1);
        float f = u - (float)i0;
        float4 tv = s_tab[i0];
        float w0 = fmaf(f, tv.z - tv.x, tv.x);
        float w1 = fmaf(f, tv.w - tv.y, tv.y);

        float a  = eattr[e];
        float cv = w0 * a;
        float m0 = cv * ns.x, m1 = cv * ns.y, m2 = cv * ns.z, m3 = w1 * a * ns.w;
        asm volatile("red.global.add.v4.f32 [%0], {%1, %2, %3, %4};"
                     :: "l"(&g_agg[4 * t]), "f"(m0), "f"(m1), "f"(m2), "f"(m3)
                     : "memory");
    }
}

// ================= kernel 3: node MLP + pooling + (last block) head ==============
__global__ void node_final_kernel(const float* __restrict__ lw1, const float* __restrict__ lb1,
                                  const float* __restrict__ lw2, const float* __restrict__ lb2,
                                  const int* __restrict__ bw, int n, float inv_norm,
                                  const float* __restrict__ fw1, const float* __restrict__ fb1,
                                  const float* __restrict__ fw2, const float* __restrict__ fb2,
                                  float* __restrict__ out, int G) {
    __shared__ float s_w1[4 * 32];
    __shared__ float s_b1[32];
    __shared__ float s_w2[32 * 16];
    __shared__ float s_b2[16];
    __shared__ int s_last;
    int tid = threadIdx.x;
    for (int i = tid; i < 128; i += blockDim.x) s_w1[i] = lw1[i];
    for (int i = tid; i < 512; i += blockDim.x) s_w2[i] = lw2[i];
    if (tid < 32) s_b1[tid] = lb1[tid];
    if (tid < 16) s_b2[tid] = lb2[tid];
    __syncthreads();

    int i = blockIdx.x * blockDim.x + tid;
    bool valid = (i < n);
    int g = 0;
    float h2[16];
#pragma unroll
    for (int j = 0; j < 16; j++) h2[j] = 0.0f;

    if (valid) {
        float4 av = *(const float4*)&g_agg[4 * i];
        float a0 = fmaxf(av.x * inv_norm, 0.0f);
        float a1 = fmaxf(av.y * inv_norm, 0.0f);
        float a2 = fmaxf(av.z * inv_norm, 0.0f);
        float a3 = fmaxf(av.w * inv_norm, 0.0f);
        float h1[32];
#pragma unroll
        for (int j = 0; j < 32; j++) {
            float acc = s_b1[j];
            acc = fmaf(a0, s_w1[j], acc);
            acc = fmaf(a1, s_w1[32 + j], acc);
            acc = fmaf(a2, s_w1[64 + j], acc);
            acc = fmaf(a3, s_w1[96 + j], acc);
            h1[j] = fmaxf(acc, 0.0f);
        }
#pragma unroll
        for (int j = 0; j < 16; j++) {
            float acc = s_b2[j];
#pragma unroll
            for (int c = 0; c < 32; c++) acc = fmaf(h1[c], s_w2[c * 16 + j], acc);
            h2[j] = fmaxf(acc, 0.0f);
        }
        g = g_b64 ? bw[2 * i] : bw[i];
    }

    // batch sorted -> whole warps usually share g: warp-reduce, 32x fewer atomics
    unsigned full = 0xffffffffu;
    unsigned mask = __ballot_sync(full, valid);
    int lane = tid & 31;
    int g0 = __shfl_sync(full, g, 0);
    bool allsame = (mask == full) && __all_sync(full, g == g0);
    if (allsame) {
#pragma unroll
        for (int j = 0; j < 16; j++) {
            float v = h2[j];
#pragma unroll
            for (int o = 16; o > 0; o >>= 1) v += __shfl_xor_sync(full, v, o);
            if (lane == j) atomicAdd(&g_sums[g0 * 16 + j], v);
        }
        if (lane == 0) atomicAdd(&g_cnt[g0], 32.0f);
    } else if (valid) {
#pragma unroll
        for (int j = 0; j < 16; j++) atomicAdd(&g_sums[g * 16 + j], h2[j]);
        atomicAdd(&g_cnt[g], 1.0f);
    }

    // ---- last block computes the per-graph head ----
    __syncthreads();
    if (tid == 0) {
        __threadfence();
        int old = atomicAdd(&g_done, 1);
        s_last = (old == (int)gridDim.x - 1) ? 1 : 0;
    }
    __syncthreads();
    if (s_last && tid < G) {
        __threadfence();
        int gg = tid;
        float c = fmaxf(g_cnt[gg], 1.0f);
        float inv = 1.0f / c;
        float p[16];
#pragma unroll
        for (int j = 0; j < 16; j++) p[j] = g_sums[gg * 16 + j] * inv;
        float t[32];
#pragma unroll
        for (int j = 0; j < 32; j++) {
            float acc = fb1[j];
#pragma unroll
            for (int c2 = 0; c2 < 16; c2++) acc = fmaf(p[c2], fw1[c2 * 32 + j], acc);
            t[j] = fmaxf(acc, 0.0f);
        }
#pragma unroll
        for (int k = 0; k < 3; k++) {
            float acc = fb2[k];
#pragma unroll
            for (int c2 = 0; c2 < 32; c2++) acc = fmaf(t[c2], fw2[c2 * 3 + k], acc);
            out[gg * 3 + k] = acc;
        }
    }
}

// ---------------- launch ----------------
extern "C" void kernel_launch(void* const* d_in, const int* in_sizes, int n_in,
                              void* d_out, int out_size) {
    const float* pos   = (const float*)d_in[0];
    const float* z     = (const float*)d_in[1];
    const float* eattr = (const float*)d_in[2];
    const int*   eidx  = (const int*)d_in[3];
    const int*   bw    = (const int*)d_in[4];   // batch words (int32 or int64; probed)
    const float* rw1 = (const float*)d_in[5];
    const float* rb1 = (const float*)d_in[6];
    const float* rw2 = (const float*)d_in[7];
    const float* rb2 = (const float*)d_in[8];
    const float* rw3 = (const float*)d_in[9];
    const float* lw1 = (const float*)d_in[10];
    const float* lb1 = (const float*)d_in[11];
    const float* lw2 = (const float*)d_in[12];
    const float* lb2 = (const float*)d_in[13];
    const float* fw1 = (const float*)d_in[14];
    const float* fb1 = (const float*)d_in[15];
    const float* fw2 = (const float*)d_in[16];
    const float* fb2 = (const float*)d_in[17];

    int n = in_sizes[1];          // N nodes (z has N elements)
    int E = in_sizes[2];          // edges (edge_attr has E elements)
    int G = out_size / 3;         // graphs
    float inv_norm = sqrtf((float)n / (float)E);   // agg / sqrt(E/N)

    int bprep = (n + 255) / 256;
    int bbuild = TABLE_N / TILE;                    // 64 blocks
    prep_build_kernel<<<bprep + bbuild, 256>>>(pos, z, bw, n, G, bprep,
                                               rw1, rb1, rw2, rb2, rw3);

    int eb = (E + 255) / 256;
    int egrid = eb < 1216 ? eb : 1216;              // 152 SMs x 8 blocks
    edge_kernel<<<egrid, 256>>>(eattr, eidx, E);

    node_final_kernel<<<(n + 255) / 256, 256>>>(lw1, lb1, lw2, lb2, bw, n, inv_norm,
                                                fw1, fb1, fw2, fb2, (float*)d_out, G);
}

// round 7
// speedup vs baseline: 5.4765x; 1.0883x over previous
#include <cuda_runtime.h>
#include <math.h>

// ---------------- scratch (no allocations allowed) ----------------
#define TABLE_N 512
#define MAX_TAB 4.5f
#define HID 100
#define TILE 8             // table entries per build block (computes TILE+1)
#define MAXN 65536
#define MAXG 256

__device__ __align__(16) float4 g_tab4[TABLE_N + 1];   // (w0_i,w1_i,w0_{i+1},w1_{i+1})
__device__ __align__(16) float4 g_node4[MAXN];         // packed (pos.xyz, z)
__device__ __align__(16) float g_agg[MAXN * 4];        // scatter-add target [N,4]
__device__ float g_sums[MAXG * 16];                    // pooled sums [G,16]
__device__ float g_cnt[MAXG];                          // node counts per graph
__device__ int   g_b64;                                // 1 if batch array is int64
__device__ int   g_done;                               // node-block completion counter

__device__ __forceinline__ float swishf(float x) {
    return x / (1.0f + __expf(-x));
}

// ================= kernel 1: build table (blocks 0..bbuild) + prep (rest) ==============
// Build blocks FIRST so they start in wave 1 — they are the latency tail.
__global__ void __launch_bounds__(256, 1)
prep_build_kernel(const float* __restrict__ pos, const float* __restrict__ z,
                  const int* __restrict__ bw, int n, int G, int bbuild,
                  const float* __restrict__ rw1, const float* __restrict__ rb1,
                  const float* __restrict__ rw2, const float* __restrict__ rb2,
                  const float* __restrict__ rw3) {
    __shared__ float s_h1[(TILE + 1) * HID];        // stage1 out; reused for half-sums
    __shared__ float s_part[4][TILE + 1][2];
    __shared__ float s_w[TILE + 1][2];
    int tid = threadIdx.x;

    if (blockIdx.x >= (unsigned)bbuild) {
        int i = (blockIdx.x - bbuild) * 256 + tid;
        if (i < n) {
            g_node4[i] = make_float4(pos[3 * i], pos[3 * i + 1], pos[3 * i + 2], z[i]);
            ((float4*)g_agg)[i] = make_float4(0.f, 0.f, 0.f, 0.f);
        }
        if (i < G * 16) g_sums[i] = 0.0f;
        if (i < G) g_cnt[i] = 0.0f;
        if (i == 0) {
            g_done = 0;
            // batch sorted in [0,G). int64 LE -> odd words are zero high-words.
            int i1 = (n / 4) | 1, i2 = (n / 2) | 1, i3 = (3 * n / 4) | 1;
            g_b64 = (bw[i1] == 0 && bw[i2] == 0 && bw[i3] == 0) ? 1 : 0;
        }
        return;
    }

    // ---------- table build: TILE+1 entries per block ----------
    int base = blockIdx.x * TILE;
    const int EC = TILE + 1;

    // stage 1: h1[e][i] = swish(basis(d_e) @ rw1 + rb1),  EC*HID pairs / 256 thr
    for (int p = tid; p < EC * HID; p += 256) {
        int e = p / HID, j = p - e * HID;
        float d = (MAX_TAB / (float)TABLE_N) * (float)(base + e);
        float acc = rb1[j];
#pragma unroll
        for (int b = 0; b < 3; b++) {
            float diff = (d - 1.5f * (float)b) * (1.0f / 1.5f);
            float c = cospif(0.5f * diff);
            float bas = (fabsf(diff) < 1.0f) ? c * c : 0.0f;
            acc = fmaf(bas, rw1[b * HID + j], acc);
        }
        s_h1[p] = swishf(acc);
    }
    __syncthreads();

    // stage 2: split the i-sum across two halves (tid>>7), j = tid & 127
    int jj = tid & 127;
    int half = tid >> 7;                  // 0 or 1
    bool live = (jj < HID);
    int j = live ? jj : 0;
    float acc[EC];
    float init = (live && half == 0) ? rb2[j] : 0.0f;
#pragma unroll
    for (int e = 0; e < EC; e++) acc[e] = init;
    int i0 = half * (HID / 2), i1 = i0 + (HID / 2);
    if (live) {
#pragma unroll 2
        for (int i = i0; i < i1; i++) {
            float w = rw2[i * HID + j];
#pragma unroll
            for (int e = 0; e < EC; e++) acc[e] = fmaf(s_h1[e * HID + i], w, acc[e]);
        }
    }
    __syncthreads();          // s_h1 free; reuse for half-1 partials
    if (half == 1 && live) {
#pragma unroll
        for (int e = 0; e < EC; e++) s_h1[j * EC + e] = acc[e];
    }
    __syncthreads();

    if (half == 0) {
        float r0 = live ? rw3[2 * j] : 0.0f;
        float r1 = live ? rw3[2 * j + 1] : 0.0f;
        int lane = tid & 31, wid = tid >> 5;   // warps 0..3
#pragma unroll
        for (int e = 0; e < EC; e++) {
            float tot = acc[e] + (live ? s_h1[j * EC + e] : 0.0f);
            float s = live ? swishf(tot) : 0.0f;
            float v0 = s * r0, v1 = s * r1;
#pragma unroll
            for (int o = 16; o > 0; o >>= 1) {
                v0 += __shfl_xor_sync(0xffffffffu, v0, o);
                v1 += __shfl_xor_sync(0xffffffffu, v1, o);
            }
            if (lane == 0) { s_part[wid][e][0] = v0; s_part[wid][e][1] = v1; }
        }
    }
    __syncthreads();
    if (tid < EC) {
        s_w[tid][0] = s_part[0][tid][0] + s_part[1][tid][0] + s_part[2][tid][0] + s_part[3][tid][0];
        s_w[tid][1] = s_part[0][tid][1] + s_part[1][tid][1] + s_part[2][tid][1] + s_part[3][tid][1];
    }
    __syncthreads();
    if (tid < TILE) {
        int idx = base + tid;
        if (idx < TABLE_N)
            g_tab4[idx] = make_float4(s_w[tid][0], s_w[tid][1], s_w[tid + 1][0], s_w[tid + 1][1]);
    }
}

// ================= kernel 2: per-edge, persistent, smem table ==============
__global__ void edge_kernel(const float* __restrict__ eattr, const int* __restrict__ eidx,
                            int E) {
    __shared__ float4 s_tab[TABLE_N];
    int tid = threadIdx.x;
    for (int i = tid; i < TABLE_N; i += blockDim.x) s_tab[i] = __ldg(&g_tab4[i]);
    __syncthreads();

    int stride = gridDim.x * blockDim.x;
    for (int e = blockIdx.x * blockDim.x + tid; e < E; e += stride) {
        int s = eidx[e];
        int t = eidx[E + e];

        float4 ns = __ldg(&g_node4[s]);
        float4 nt = __ldg(&g_node4[t]);
        float dx = ns.x - nt.x;
        float dy = ns.y - nt.y;
        float dz = ns.z - nt.z;
        float d = sqrtf(fmaf(dx, dx, fmaf(dy, dy, fmaf(dz, dz, 1e-12f))));

        float u = d * ((float)TABLE_N / MAX_TAB);
        u = fminf(u, (float)TABLE_N);
        int i0 = min((int)u, TABLE_N - 1);
        float f = u - (float)i0;
        float4 tv = s_tab[i0];
        float w0 = fmaf(f, tv.z - tv.x, tv.x);
        float w1 = fmaf(f, tv.w - tv.y, tv.y);

        float a  = eattr[e];
        float cv = w0 * a;
        float m0 = cv * ns.x, m1 = cv * ns.y, m2 = cv * ns.z, m3 = w1 * a * ns.w;
        asm volatile("red.global.add.v4.f32 [%0], {%1, %2, %3, %4};"
                     :: "l"(&g_agg[4 * t]), "f"(m0), "f"(m1), "f"(m2), "f"(m3)
                     : "memory");
    }
}

// ================= kernel 3: node MLP + pooling + (last block) head ==============
__global__ void node_final_kernel(const float* __restrict__ lw1, const float* __restrict__ lb1,
                                  const float* __restrict__ lw2, const float* __restrict__ lb2,
                                  const int* __restrict__ bw, int n, float inv_norm,
                                  const float* __restrict__ fw1, const float* __restrict__ fb1,
                                  const float* __restrict__ fw2, const float* __restrict__ fb2,
                                  float* __restrict__ out, int G) {
    __shared__ float s_w1[4 * 32];
    __shared__ float s_b1[32];
    __shared__ float s_w2[32 * 16];
    __shared__ float s_b2[16];
    __shared__ int s_last;
    int tid = threadIdx.x;
    for (int i = tid; i < 128; i += blockDim.x) s_w1[i] = lw1[i];
    for (int i = tid; i < 512; i += blockDim.x) s_w2[i] = lw2[i];
    if (tid < 32) s_b1[tid] = lb1[tid];
    if (tid < 16) s_b2[tid] = lb2[tid];
    __syncthreads();

    int i = blockIdx.x * blockDim.x + tid;
    bool valid = (i < n);
    int g = 0;
    float h2[16];
#pragma unroll
    for (int j = 0; j < 16; j++) h2[j] = 0.0f;

    if (valid) {
        float4 av = *(const float4*)&g_agg[4 * i];
        float a0 = fmaxf(av.x * inv_norm, 0.0f);
        float a1 = fmaxf(av.y * inv_norm, 0.0f);
        float a2 = fmaxf(av.z * inv_norm, 0.0f);
        float a3 = fmaxf(av.w * inv_norm, 0.0f);
        float h1[32];
#pragma unroll
        for (int j = 0; j < 32; j++) {
            float acc = s_b1[j];
            acc = fmaf(a0, s_w1[j], acc);
            acc = fmaf(a1, s_w1[32 + j], acc);
            acc = fmaf(a2, s_w1[64 + j], acc);
            acc = fmaf(a3, s_w1[96 + j], acc);
            h1[j] = fmaxf(acc, 0.0f);
        }
#pragma unroll
        for (int j = 0; j < 16; j++) {
            float acc = s_b2[j];
#pragma unroll
            for (int c = 0; c < 32; c++) acc = fmaf(h1[c], s_w2[c * 16 + j], acc);
            h2[j] = fmaxf(acc, 0.0f);
        }
        g = g_b64 ? bw[2 * i] : bw[i];
    }

    // batch sorted -> whole warps usually share g: warp-reduce, 32x fewer atomics
    unsigned full = 0xffffffffu;
    unsigned mask = __ballot_sync(full, valid);
    int lane = tid & 31;
    int g0 = __shfl_sync(full, g, 0);
    bool allsame = (mask == full) && __all_sync(full, g == g0);
    if (allsame) {
#pragma unroll
        for (int j = 0; j < 16; j++) {
            float v = h2[j];
#pragma unroll
            for (int o = 16; o > 0; o >>= 1) v += __shfl_xor_sync(full, v, o);
            if (lane == j) atomicAdd(&g_sums[g0 * 16 + j], v);
        }
        if (lane == 0) atomicAdd(&g_cnt[g0], 32.0f);
    } else if (valid) {
#pragma unroll
        for (int j = 0; j < 16; j++) atomicAdd(&g_sums[g * 16 + j], h2[j]);
        atomicAdd(&g_cnt[g], 1.0f);
    }

    // ---- last block computes the per-graph head ----
    __syncthreads();
    if (tid == 0) {
        __threadfence();
        int old = atomicAdd(&g_done, 1);
        s_last = (old == (int)gridDim.x - 1) ? 1 : 0;
    }
    __syncthreads();
    if (s_last && tid < G) {
        __threadfence();
        int gg = tid;
        float c = fmaxf(g_cnt[gg], 1.0f);
        float inv = 1.0f / c;
        float p[16];
#pragma unroll
        for (int j = 0; j < 16; j++) p[j] = g_sums[gg * 16 + j] * inv;
        float t[32];
#pragma unroll
        for (int j = 0; j < 32; j++) {
            float acc = fb1[j];
#pragma unroll
            for (int c2 = 0; c2 < 16; c2++) acc = fmaf(p[c2], fw1[c2 * 32 + j], acc);
            t[j] = fmaxf(acc, 0.0f);
        }
#pragma unroll
        for (int k = 0; k < 3; k++) {
            float acc = fb2[k];
#pragma unroll
            for (int c2 = 0; c2 < 32; c2++) acc = fmaf(t[c2], fw2[c2 * 3 + k], acc);
            out[gg * 3 + k] = acc;
        }
    }
}

// ---------------- launch ----------------
extern "C" void kernel_launch(void* const* d_in, const int* in_sizes, int n_in,
                              void* d_out, int out_size) {
    const float* pos   = (const float*)d_in[0];
    const float* z     = (const float*)d_in[1];
    const float* eattr = (const float*)d_in[2];
    const int*   eidx  = (const int*)d_in[3];
    const int*   bw    = (const int*)d_in[4];   // batch words (int32 or int64; probed)
    const float* rw1 = (const float*)d_in[5];
    const float* rb1 = (const float*)d_in[6];
    const float* rw2 = (const float*)d_in[7];
    const float* rb2 = (const float*)d_in[8];
    const float* rw3 = (const float*)d_in[9];
    const float* lw1 = (const float*)d_in[10];
    const float* lb1 = (const float*)d_in[11];
    const float* lw2 = (const float*)d_in[12];
    const float* lb2 = (const float*)d_in[13];
    const float* fw1 = (const float*)d_in[14];
    const float* fb1 = (const float*)d_in[15];
    const float* fw2 = (const float*)d_in[16];
    const float* fb2 = (const float*)d_in[17];

    int n = in_sizes[1];          // N nodes (z has N elements)
    int E = in_sizes[2];          // edges (edge_attr has E elements)
    int G = out_size / 3;         // graphs
    float inv_norm = sqrtf((float)n / (float)E);   // agg / sqrt(E/N)

    int bprep = (n + 255) / 256;
    int bbuild = TABLE_N / TILE;                    // 64 blocks, scheduled FIRST
    prep_build_kernel<<<bbuild + bprep, 256>>>(pos, z, bw, n, G, bbuild,
                                               rw1, rb1, rw2, rb2, rw3);

    int eb = (E + 255) / 256;
    int egrid = eb < 1216 ? eb : 1216;              // 152 SMs x 8 blocks
    edge_kernel<<<egrid, 256>>>(eattr, eidx, E);

    node_final_kernel<<<(n + 255) / 256, 256>>>(lw1, lb1, lw2, lb2, bw, n, inv_norm,
                                                fw1, fb1, fw2, fb2, (float*)d_out, G);
}